// round 11
// baseline (speedup 1.0000x reference)
#include <cuda_runtime.h>

// Histogram2d: x[32,16384,64] f32 in [0,1) -> hist[32,128,64] * weights[128,64]
//
// Hist: 256-thread blocks, 8 warps = 8 row-offsets; lane l loads float2
// (features 2l, 2l+1) -> one warp covers a full row per LDG.64 (halves the
// LDG instruction count vs scalar loads). Each thread owns TWO per-thread u8
// histograms, both bank-aligned to lane l -> all RMWs conflict-free. Dump:
// u16x2-packed REDG atomicAdd into a 512KB per-batch accumulator (carry-free:
// per-bin batch total <= 16384 < 2^16). Finalize applies weights and restores
// the accumulator to zero for the next graph replay.

constexpr int B = 32, S = 16384, F = 64, BINS = 128;
constexpr int NCHUNK = 13;             // 12*1280 + 1024 = 16384
constexpr int CHUNK = 1280;            // iters = 160/128 (<=255 u8-safe, %8==0)
constexpr int THREADS = 256;           // 8 warps; warp w = row offset w (0..7)
// smem: 8 warps x 2048 words. word(w, h, m, l) = w*2048 + h*1024 + m*32 + l
// (bank = l for every mainloop access)
constexpr int SMEM_BYTES = 8 * 2048 * 4;           // 65536 B -> 3 blocks/SM (24 warps)

// u16x2-packed accumulators: word W = q*64 + f holds bins (2q, 2q+1) of feature f.
constexpr int PWORDS = (BINS / 2) * F;             // 4096 words per batch
__device__ __align__(16) unsigned int g_accum[(size_t)B * PWORDS];  // 512 KB, starts 0

__global__ __launch_bounds__(THREADS, 3)
void hist_kernel(const float* __restrict__ x) {
    extern __shared__ unsigned int sh[];
    const int tid = threadIdx.x;
    const int w = tid >> 5, l = tid & 31;

    // zero the block's histograms (uint4 stores, conflict-free)
    uint4* sh4 = reinterpret_cast<uint4*>(sh);
#pragma unroll
    for (int k = 0; k < 16; k++) sh4[tid + THREADS * k] = make_uint4(0u, 0u, 0u, 0u);
    __syncthreads();   // warps share no hist words, but zeroing used block-stride

    unsigned char* sb = reinterpret_cast<unsigned char*>(sh);
    const unsigned int tbase0 = (w << 13) + (l << 2);   // hist of feature 2l
    const unsigned int tbase1 = tbase0 + 4096;          // hist of feature 2l+1

    const int b = blockIdx.y, c = blockIdx.x;
    const int row0 = c * CHUNK;
    const int rows = min(CHUNK, S - row0);   // 1280 or 1024
    const int iters = rows >> 3;             // 160 or 128 (%8==0) -> u8 safe

    // lane l -> float2 covering features (2l, 2l+1) of row (row0 + w + 8*i)
    const float2* base = reinterpret_cast<const float2*>(
        x + ((size_t)b * S + row0 + w) * F) + l;

    constexpr int U = 8;                     // load-ahead for MLP
#pragma unroll 1
    for (int i = 0; i < iters; i += U) {
        float2 v[U];
#pragma unroll
        for (int u = 0; u < U; u++)
            v[u] = __ldcs(base + (size_t)(i + u) * (8 * F / 2));
#pragma unroll
        for (int u = 0; u < U; u++) {
            // exact trunc(v*128): RZ-add truncates mantissa; bin bits = [16:23)
            const unsigned int bx = __float_as_uint(__fadd_rz(v[u].x, 1.0f));
            const unsigned int ox = (((bx >> 18) & 31u) << 7) | ((bx >> 16) & 3u);
            sb[tbase0 + ox] = (unsigned char)(sb[tbase0 + ox] + 1);   // bank l
            const unsigned int by = __float_as_uint(__fadd_rz(v[u].y, 1.0f));
            const unsigned int oy = (((by >> 18) & 31u) << 7) | ((by >> 16) & 3u);
            sb[tbase1 + oy] = (unsigned char)(sb[tbase1 + oy] + 1);   // bank l
        }
    }
    __syncthreads();

    // Reduction over 8 warps (dp4a byte extraction), u16x2-packed REDG dump.
    // Per-bin block partial <= 8*160 = 1280 < 2^16; batch total <= 16384.
    unsigned int* outp = g_accum + (size_t)b * PWORDS;
#pragma unroll
    for (int k = 0; k < 8; k++) {
        const int u = tid + THREADS * k;     // 0..2047
        const int fo = u & 63;
        const int m  = u >> 6;               // -> bins 4m..4m+3
        const unsigned int src = ((fo & 1) << 10) + (m << 5) + (fo >> 1);
        unsigned int s0 = 0, s1 = 0, s2 = 0, s3 = 0;
#pragma unroll
        for (int wr = 0; wr < 8; wr++) {
            const unsigned int v = sh[(wr << 11) + src];
            s0 = __dp4a(v, 0x00000001u, s0);
            s1 = __dp4a(v, 0x00000100u, s1);
            s2 = __dp4a(v, 0x00010000u, s2);
            s3 = __dp4a(v, 0x01000000u, s3);
        }
        atomicAdd(&outp[(2 * m + 0) * F + fo], s0 | (s1 << 16));   // REDG, no return
        atomicAdd(&outp[(2 * m + 1) * F + fo], s2 | (s3 << 16));
    }
}

__global__ __launch_bounds__(256)
void finalize_kernel(const float* __restrict__ wts, float* __restrict__ out) {
    // idx over B x 1024 uint4-groups: 32768 threads, 128 blocks.
    const int idx = blockIdx.x * 256 + threadIdx.x;
    const int b = idx >> 10;
    const int g = idx & 1023;                // uint4 group: words 4g..4g+3
    const int q  = g >> 4;                   // bin pair -> bins 2q, 2q+1
    const int f4 = (g & 15) << 2;            // feature group start

    uint4* pa = reinterpret_cast<uint4*>(g_accum + (size_t)b * PWORDS) + g;
    const uint4 v = *pa;
    *pa = make_uint4(0u, 0u, 0u, 0u);        // restore zero for next replay

    const float4 wlo = *reinterpret_cast<const float4*>(wts + (2 * q) * F + f4);
    const float4 whi = *reinterpret_cast<const float4*>(wts + (2 * q + 1) * F + f4);
    float4 olo, ohi;
    olo.x = (float)(v.x & 0xFFFFu) * wlo.x;  ohi.x = (float)(v.x >> 16) * whi.x;
    olo.y = (float)(v.y & 0xFFFFu) * wlo.y;  ohi.y = (float)(v.y >> 16) * whi.y;
    olo.z = (float)(v.z & 0xFFFFu) * wlo.z;  ohi.z = (float)(v.z >> 16) * whi.z;
    olo.w = (float)(v.w & 0xFFFFu) * wlo.w;  ohi.w = (float)(v.w >> 16) * whi.w;
    float* ob = out + ((size_t)b * BINS + 2 * q) * F + f4;
    *reinterpret_cast<float4*>(ob)     = olo;
    *reinterpret_cast<float4*>(ob + F) = ohi;
}

extern "C" void kernel_launch(void* const* d_in, const int* in_sizes, int n_in,
                              void* d_out, int out_size) {
    const float* x   = (const float*)d_in[0];
    const float* wts = (const float*)d_in[1];
    float* out = (float*)d_out;

    cudaFuncSetAttribute(hist_kernel, cudaFuncAttributeMaxDynamicSharedMemorySize, SMEM_BYTES);

    dim3 grid(NCHUNK, B);   // 13 x 32 = 416 blocks, single wave at occ 3
    hist_kernel<<<grid, THREADS, SMEM_BYTES>>>(x);
    finalize_kernel<<<(B * 1024) / 256, 256>>>(wts, out);
}

// round 12
// speedup vs baseline: 1.1463x; 1.1463x over previous
#include <cuda_runtime.h>

// Histogram2d: x[32,16384,64] f32 in [0,1) -> hist[32,128,64] * weights[128,64]
//
// Hist (mainloop/occupancy identical to the 33.3us round-10 winner):
// 512-thread blocks (2 feature-halves x 8 row-offsets), NCHUNK=13 -> 416
// blocks, single wave at occ 3 (48 warps/SM). Per-thread private u8
// histograms in SMEM, bank-aligned (lane l always hits bank l -> conflict-
// free RMWs). Dump: u16x4-in-u64 packed REDG atomicAdd into a 512KB
// per-batch accumulator (carry-free: each u16 field <= 16384 < 2^16, low
// u32 < 2^32 -> no cross-field carry). Finalize applies weights and
// restores the accumulator to zero for the next graph replay.

constexpr int B = 32, S = 16384, F = 64, BINS = 128;
constexpr int NCHUNK = 13;             // 12*1280 + 1024 = 16384
constexpr int CHUNK = 1280;            // iters = 160/128 (<=255 u8-safe, %8==0)
constexpr int THREADS = 512;           // 16 warps: fh = w&1, soff = w>>1 (0..7)
// smem: 16 warps x 1024 words. word(w, m, l) = w*1024 + m*32 + l  (bank = l)
constexpr int SMEM_BYTES = 16 * 1024 * 4;          // 65536 B -> 3 blocks/SM (48 warps)

// u64 accumulators: word W64 = m*64 + f holds bins (4m..4m+3) of feature f:
// lo32 = bins(4m,4m+1) u16x2, hi32 = bins(4m+2,4m+3) u16x2.
constexpr int P64 = (BINS / 4) * F;                // 2048 u64 per batch
__device__ __align__(16) unsigned long long g_accum[(size_t)B * P64];  // 512 KB, starts 0

__global__ __launch_bounds__(THREADS, 3)
void hist_kernel(const float* __restrict__ x) {
    extern __shared__ unsigned int sh[];
    const int tid = threadIdx.x;
    const int w = tid >> 5, l = tid & 31;

    // zero own histogram: word (w, m, l) -> bank l, conflict-free, private
#pragma unroll
    for (int m = 0; m < 32; m++) sh[(w << 10) + (m << 5) + l] = 0u;

    unsigned char* sb = reinterpret_cast<unsigned char*>(sh);
    const unsigned int tbase = (w << 12) + (l << 2);   // byte base of this lane's hist

    const int fh = w & 1;        // feature half: 0 -> f 0..31, 1 -> f 32..63
    const int soff = w >> 1;     // row offset mod 8
    const int f = fh * 32 + l;
    const int b = blockIdx.y, c = blockIdx.x;

    const int row0 = c * CHUNK;
    const int rows = min(CHUNK, S - row0);   // 1280 or 1024
    const int iters = rows >> 3;             // 160 or 128 (%8==0) -> u8 safe
    const float* base = x + (((size_t)b * S + row0 + soff) * F + f);

    constexpr int U = 8;                     // load-ahead for MLP
#pragma unroll 1
    for (int i = 0; i < iters; i += U) {
        float v[U];
#pragma unroll
        for (int u = 0; u < U; u++)
            v[u] = __ldcs(base + (size_t)(i + u) * (8 * F));
#pragma unroll
        for (int u = 0; u < U; u++) {
            // exact trunc(v*128): RZ-add truncates mantissa; bin bits = [16:23)
            const unsigned int bits = __float_as_uint(__fadd_rz(v[u], 1.0f));
            // byte offset ((bin>>2)<<7) | (bin&3): keeps this lane in bank l
            const unsigned int off = (((bits >> 18) & 31u) << 7) | ((bits >> 16) & 3u);
            sb[tbase + off] = (unsigned char)(sb[tbase + off] + 1);
        }
    }
    __syncthreads();

    // Intra-block reduction over 8 row-offsets (dp4a byte extraction),
    // one u64 REDG per (4-bin group, feature): 8 REDGs/thread, coalesced.
    // Per-bin block partial <= 8*160 = 1280; batch total <= 16384 < 2^16.
    // smem loads hit bank fl = lane -> conflict-free.
    unsigned long long* outp = g_accum + (size_t)b * P64;
#pragma unroll
    for (int k = 0; k < 4; k++) {
        const int u = tid + THREADS * k;     // 0..2047
        const int fo = u & 63;
        const int m  = u >> 6;               // -> bins 4m..4m+3
        const int fh2 = fo >> 5, fl = fo & 31;
        unsigned int s0 = 0, s1 = 0, s2 = 0, s3 = 0;
#pragma unroll
        for (int s = 0; s < 8; s++) {
            const unsigned int v = sh[((2 * s + fh2) << 10) + (m << 5) + fl];
            s0 = __dp4a(v, 0x00000001u, s0);
            s1 = __dp4a(v, 0x00000100u, s1);
            s2 = __dp4a(v, 0x00010000u, s2);
            s3 = __dp4a(v, 0x01000000u, s3);
        }
        const unsigned long long val =
            (unsigned long long)(s0 | (s1 << 16)) |
            ((unsigned long long)(s2 | (s3 << 16)) << 32);
        atomicAdd(&outp[m * F + fo], val);   // RED.E.ADD.64, no return
    }
}

__global__ __launch_bounds__(256)
void finalize_kernel(const float* __restrict__ wts, float* __restrict__ out) {
    // One thread per u64 accumulator word: B*2048 = 65536 threads, 256 blocks.
    const int idx = blockIdx.x * 256 + threadIdx.x;
    const int b   = idx >> 11;
    const int W64 = idx & 2047;              // m*64 + fo
    const int m   = W64 >> 6;                // bins 4m..4m+3
    const int fo  = W64 & 63;

    uint2* pa = reinterpret_cast<uint2*>(g_accum) + idx;   // coalesced
    const uint2 v = *pa;
    *pa = make_uint2(0u, 0u);                // restore zero for next replay

    const float* wb = wts + (4 * m) * F + fo;
    float* ob = out + ((size_t)b * BINS + 4 * m) * F + fo;
    ob[0 * F] = (float)(v.x & 0xFFFFu) * wb[0 * F];
    ob[1 * F] = (float)(v.x >> 16)     * wb[1 * F];
    ob[2 * F] = (float)(v.y & 0xFFFFu) * wb[2 * F];
    ob[3 * F] = (float)(v.y >> 16)     * wb[3 * F];
}

extern "C" void kernel_launch(void* const* d_in, const int* in_sizes, int n_in,
                              void* d_out, int out_size) {
    const float* x   = (const float*)d_in[0];
    const float* wts = (const float*)d_in[1];
    float* out = (float*)d_out;

    cudaFuncSetAttribute(hist_kernel, cudaFuncAttributeMaxDynamicSharedMemorySize, SMEM_BYTES);

    dim3 grid(NCHUNK, B);   // 13 x 32 = 416 blocks, single wave at occ 3
    hist_kernel<<<grid, THREADS, SMEM_BYTES>>>(x);
    finalize_kernel<<<(B * P64) / 256, 256>>>(wts, out);
}